// round 2
// baseline (speedup 1.0000x reference)
#include <cuda_runtime.h>
#include <math.h>

#define N_NODES 100000
#define N_EDGES 1600000
#define D_FEAT  64
#define D_F2    32          // D_FEAT / 2 (float2 elements per row)
#define EPS     1e-7f

// Scratch (no allocation allowed anywhere)
__device__ float g_norm[N_NODES];
__device__ float g_sim[N_EDGES];
__device__ int   g_rowptr[N_NODES + 1];
__device__ int   g_is64;     // 1 if edge indices are int64, 0 if int32

// ---------------------------------------------------------------------------
// Index fetch that works for either int32 or int64 edge buffers.
// ---------------------------------------------------------------------------
__device__ __forceinline__ int get_idx(const void* p, int e, int is64)
{
    if (is64) return (int)((const long long*)p)[e];
    return ((const int*)p)[e];
}

// ---------------------------------------------------------------------------
// Kernel 0: detect index dtype. edge_col is uniform random in [0, N_NODES).
// If stored as int64, every odd 32-bit word (high half) is zero. If int32,
// odd words are random values — P(all 128 odd words zero) ~ (1e-5)^128 = 0.
// ---------------------------------------------------------------------------
__global__ void detect_kernel(const unsigned int* __restrict__ ec_raw)
{
    if (blockIdx.x == 0 && threadIdx.x == 0) {
        int nz = 0;
        #pragma unroll 8
        for (int i = 1; i < 256; i += 2) nz += (ec_raw[i] != 0u);
        g_is64 = (nz == 0) ? 1 : 0;
    }
}

// ---------------------------------------------------------------------------
// Kernel 1: per-node L2 norms. One warp per node, float2 loads.
// ---------------------------------------------------------------------------
__global__ void norm_kernel(const float2* __restrict__ x)
{
    int warp = (blockIdx.x * blockDim.x + threadIdx.x) >> 5;
    int lane = threadIdx.x & 31;
    if (warp >= N_NODES) return;

    float2 a = x[warp * D_F2 + lane];
    float s = a.x * a.x + a.y * a.y;
    #pragma unroll
    for (int o = 16; o; o >>= 1) s += __shfl_xor_sync(0xffffffffu, s, o);
    if (lane == 0) g_norm[warp] = sqrtf(s);
}

// ---------------------------------------------------------------------------
// Kernel 2: CSR row pointers from sorted edge_row via binary search.
// ---------------------------------------------------------------------------
__global__ void rowptr_kernel(const void* __restrict__ edge_row)
{
    int i = blockIdx.x * blockDim.x + threadIdx.x;
    if (i > N_NODES) return;

    int is64 = g_is64;
    int lo = 0, hi = N_EDGES;
    while (lo < hi) {
        int mid = (lo + hi) >> 1;
        if (get_idx(edge_row, mid, is64) < i) lo = mid + 1; else hi = mid;
    }
    g_rowptr[i] = lo;   // first edge with edge_row >= i
}

// ---------------------------------------------------------------------------
// Kernel 3: per-edge scaled cosine similarity. One warp per edge.
// ---------------------------------------------------------------------------
__global__ void sim_kernel(const float2* __restrict__ x,
                           const void* __restrict__ edge_row,
                           const void* __restrict__ edge_col,
                           const float* __restrict__ beta)
{
    int e    = (blockIdx.x * blockDim.x + threadIdx.x) >> 5;
    int lane = threadIdx.x & 31;
    if (e >= N_EDGES) return;

    int is64 = g_is64;
    int r = get_idx(edge_row, e, is64);
    int c = get_idx(edge_col, e, is64);

    float2 a = x[r * D_F2 + lane];
    float2 b = x[c * D_F2 + lane];
    float d = a.x * b.x + a.y * b.y;
    #pragma unroll
    for (int o = 16; o; o >>= 1) d += __shfl_xor_sync(0xffffffffu, d, o);

    if (lane == 0) {
        float denom = g_norm[r] * g_norm[c] + EPS;
        g_sim[e] = beta[0] * (d / denom);
    }
}

// ---------------------------------------------------------------------------
// Kernel 4: per-row softmax + SPMM. One warp per row over its sorted segment.
// out[i] = (sum_j exp(sim_ij - mx) * x[col_j]) / (sum_j exp(sim_ij - mx))
// ---------------------------------------------------------------------------
__global__ void row_kernel(const float2* __restrict__ x,
                           const void* __restrict__ edge_col,
                           float2* __restrict__ out)
{
    int row  = (blockIdx.x * blockDim.x + threadIdx.x) >> 5;
    int lane = threadIdx.x & 31;
    if (row >= N_NODES) return;

    int is64 = g_is64;
    int s  = g_rowptr[row];
    int en = g_rowptr[row + 1];

    if (s == en) {                       // empty row -> zeros (d_out poisoned)
        out[row * D_F2 + lane] = make_float2(0.f, 0.f);
        return;
    }

    // segment max (uniform broadcast loads)
    float mx = -INFINITY;
    for (int e = s; e < en; ++e) mx = fmaxf(mx, g_sim[e]);

    float2 acc = make_float2(0.f, 0.f);
    float  wsum = 0.f;
    #pragma unroll 2
    for (int e = s; e < en; ++e) {
        float  w = expf(g_sim[e] - mx);
        int    c = get_idx(edge_col, e, is64);
        float2 b = x[c * D_F2 + lane];
        acc.x += w * b.x;
        acc.y += w * b.y;
        wsum  += w;
    }
    float inv = 1.f / wsum;
    out[row * D_F2 + lane] = make_float2(acc.x * inv, acc.y * inv);
}

// ---------------------------------------------------------------------------
extern "C" void kernel_launch(void* const* d_in, const int* in_sizes, int n_in,
                              void* d_out, int out_size)
{
    // Bind inputs by element count (robust to metadata ordering):
    //   6,400,000 -> x ; 1 -> beta ; 1,600,000 (first) -> edge_row, (second) -> edge_col
    const float2* x    = 0;
    const float*  beta = 0;
    const void*   er   = 0;
    const void*   ec   = 0;
    for (int i = 0; i < n_in; ++i) {
        long long sz = in_sizes[i];
        if (sz == (long long)N_NODES * D_FEAT) x = (const float2*)d_in[i];
        else if (sz == 1)                      beta = (const float*)d_in[i];
        else if (sz == N_EDGES) {
            if (!er) er = d_in[i]; else ec = d_in[i];
        }
    }
    float2* out = (float2*)d_out;

    detect_kernel<<<1, 32>>>((const unsigned int*)ec);

    {   // 1) norms: warp per node
        int threads = 256;
        long long total = (long long)N_NODES * 32;
        int blocks = (int)((total + threads - 1) / threads);
        norm_kernel<<<blocks, threads>>>(x);
    }
    {   // 2) row pointers: thread per node (+1)
        int threads = 256;
        int blocks = (N_NODES + 1 + threads - 1) / threads;
        rowptr_kernel<<<blocks, threads>>>(er);
    }
    {   // 3) similarities: warp per edge
        int threads = 256;
        long long total = (long long)N_EDGES * 32;
        int blocks = (int)((total + threads - 1) / threads);
        sim_kernel<<<blocks, threads>>>(x, er, ec, beta);
    }
    {   // 4) softmax + SPMM: warp per row
        int threads = 256;
        long long total = (long long)N_NODES * 32;
        int blocks = (int)((total + threads - 1) / threads);
        row_kernel<<<blocks, threads>>>(x, ec, out);
    }
}

// round 3
// speedup vs baseline: 2.1704x; 2.1704x over previous
#include <cuda_runtime.h>
#include <math.h>

#define N_NODES 100000
#define N_EDGES 1600000
#define D_FEAT  64
#define D_F2    32          // float2 elements per row
#define EPS     1e-7f

// Scratch (no allocation allowed anywhere)
__device__ float2 g_xn[N_NODES * D_F2];   // x normalized to unit rows (25.6 MB)
__device__ int    g_rowptr[N_NODES + 1];
__device__ int    g_is64;                 // 1 if edge indices are int64

// ---------------------------------------------------------------------------
__device__ __forceinline__ int get_idx(const void* p, int e, int is64)
{
    if (is64) return (int)((const long long*)p)[e];
    return ((const int*)p)[e];
}

// ---------------------------------------------------------------------------
// Kernel 0: detect index dtype. edge_col values are random in [0, N_NODES);
// as int64 every high 32-bit word is 0, as int32 the odd words are random.
// ---------------------------------------------------------------------------
__global__ void detect_kernel(const unsigned int* __restrict__ ec_raw)
{
    if (blockIdx.x == 0 && threadIdx.x == 0) {
        int nz = 0;
        #pragma unroll 8
        for (int i = 1; i < 256; i += 2) nz += (ec_raw[i] != 0u);
        g_is64 = (nz == 0) ? 1 : 0;
    }
}

// ---------------------------------------------------------------------------
// Kernel 1: normalize rows. One warp per node. xn = x / ||x||.
// (sim = beta*dot(xn_r,xn_c) differs from ref's /(n_r*n_c+eps) by ~1e-9 rel.)
// ---------------------------------------------------------------------------
__global__ void normalize_kernel(const float2* __restrict__ x)
{
    int node = (blockIdx.x * blockDim.x + threadIdx.x) >> 5;
    int lane = threadIdx.x & 31;
    if (node >= N_NODES) return;

    float2 a = x[node * D_F2 + lane];
    float s = a.x * a.x + a.y * a.y;
    #pragma unroll
    for (int o = 16; o; o >>= 1) s += __shfl_xor_sync(0xffffffffu, s, o);
    float inv = rsqrtf(s);
    g_xn[node * D_F2 + lane] = make_float2(a.x * inv, a.y * inv);
}

// ---------------------------------------------------------------------------
// Kernel 2: CSR row pointers from sorted edge_row via binary search.
// ---------------------------------------------------------------------------
__global__ void rowptr_kernel(const void* __restrict__ edge_row)
{
    int i = blockIdx.x * blockDim.x + threadIdx.x;
    if (i > N_NODES) return;

    int is64 = g_is64;
    int lo = 0, hi = N_EDGES;
    while (lo < hi) {
        int mid = (lo + hi) >> 1;
        if (get_idx(edge_row, mid, is64) < i) lo = mid + 1; else hi = mid;
    }
    g_rowptr[i] = lo;
}

// ---------------------------------------------------------------------------
// Kernel 3: fused sim + online softmax + SPMM. One warp per row.
// out[i] = sum_j exp(beta*cos_ij - mx) * x[c_j] / sum_j exp(beta*cos_ij - mx)
// Note: weights apply to the ORIGINAL x[c]; we use xn[c]*norm_c... no — the
// reference SPMM uses raw B = x[col]. So gather raw x[c] too? That would
// double traffic. Instead: out uses x[c] = xn[c] * ||x[c]||; we fold the norm
// back in by gathering the raw x row once — but we already have xn[c] in
// registers and need x[c]. Solution: store norms and rescale: x[c] = xn[c]*n_c.
// ---------------------------------------------------------------------------
__device__ float g_nrm[N_NODES];

__global__ void normalize_kernel2(const float2* __restrict__ x)
{
    int node = (blockIdx.x * blockDim.x + threadIdx.x) >> 5;
    int lane = threadIdx.x & 31;
    if (node >= N_NODES) return;

    float2 a = x[node * D_F2 + lane];
    float s = a.x * a.x + a.y * a.y;
    #pragma unroll
    for (int o = 16; o; o >>= 1) s += __shfl_xor_sync(0xffffffffu, s, o);
    float nrm = sqrtf(s);
    float inv = 1.0f / nrm;
    g_xn[node * D_F2 + lane] = make_float2(a.x * inv, a.y * inv);
    if (lane == 0) g_nrm[node] = nrm;
}

__global__ void fused_row_kernel(const void* __restrict__ edge_col,
                                 const float* __restrict__ beta,
                                 float2* __restrict__ out)
{
    int row  = (blockIdx.x * blockDim.x + threadIdx.x) >> 5;
    int lane = threadIdx.x & 31;
    if (row >= N_NODES) return;

    int is64 = g_is64;
    int s  = g_rowptr[row];
    int en = g_rowptr[row + 1];

    if (s == en) {                       // empty row -> zeros
        out[row * D_F2 + lane] = make_float2(0.f, 0.f);
        return;
    }

    float2 xr = g_xn[row * D_F2 + lane];   // row features, unit norm
    float  bv = beta[0];

    float  mx   = -INFINITY;
    float  wsum = 0.f;
    float2 acc  = make_float2(0.f, 0.f);

    #pragma unroll 2
    for (int e = s; e < en; ++e) {
        int    c  = get_idx(edge_col, e, is64);
        float2 b  = g_xn[c * D_F2 + lane];
        float  nc = g_nrm[c];              // broadcast (uniform per edge)

        float d = xr.x * b.x + xr.y * b.y;
        #pragma unroll
        for (int o = 16; o; o >>= 1) d += __shfl_xor_sync(0xffffffffu, d, o);

        float sim   = bv * d;
        float m2    = fmaxf(mx, sim);
        float scale = __expf(mx - m2);     // exp(-inf - m2) = 0 on first edge
        float w     = __expf(sim - m2) * nc;  // fold ||x_c|| into weight
        wsum  = wsum * scale + __expf(sim - m2);
        acc.x = acc.x * scale + w * b.x;   // w*xn[c] == exp(...)*x[c]
        acc.y = acc.y * scale + w * b.y;
        mx = m2;
    }

    float inv = 1.f / wsum;
    out[row * D_F2 + lane] = make_float2(acc.x * inv, acc.y * inv);
}

// ---------------------------------------------------------------------------
extern "C" void kernel_launch(void* const* d_in, const int* in_sizes, int n_in,
                              void* d_out, int out_size)
{
    // Bind inputs by element count (robust to ordering):
    const float2* x    = 0;
    const float*  beta = 0;
    const void*   er   = 0;
    const void*   ec   = 0;
    for (int i = 0; i < n_in; ++i) {
        long long sz = in_sizes[i];
        if (sz == (long long)N_NODES * D_FEAT) x = (const float2*)d_in[i];
        else if (sz == 1)                      beta = (const float*)d_in[i];
        else if (sz == N_EDGES) {
            if (!er) er = d_in[i]; else ec = d_in[i];
        }
    }
    float2* out = (float2*)d_out;

    detect_kernel<<<1, 32>>>((const unsigned int*)ec);

    {   // normalize + norms: warp per node
        int threads = 256;
        long long total = (long long)N_NODES * 32;
        int blocks = (int)((total + threads - 1) / threads);
        normalize_kernel2<<<blocks, threads>>>(x);
    }
    {   // row pointers
        int threads = 256;
        int blocks = (N_NODES + 1 + threads - 1) / threads;
        rowptr_kernel<<<blocks, threads>>>(er);
    }
    {   // fused sim + softmax + SPMM: warp per row
        int threads = 256;
        long long total = (long long)N_NODES * 32;
        int blocks = (int)((total + threads - 1) / threads);
        fused_row_kernel<<<blocks, threads>>>(ec, beta, out);
    }
}

// round 4
// speedup vs baseline: 2.5084x; 1.1558x over previous
#include <cuda_runtime.h>
#include <math.h>

#define N_NODES 100000
#define N_EDGES 1600000
#define D_FEAT  64
#define D_F4    16          // float4 elements per row
#define EPS     1e-7f

// Scratch
__device__ float g_inv[N_NODES];          // 1 / ||x_i||
__device__ int   g_rowptr[N_NODES + 1];
__device__ int   g_is64;                  // 1 if edge indices are int64

// ---------------------------------------------------------------------------
__device__ __forceinline__ int get_idx(const void* p, int e, int is64)
{
    if (is64) return (int)((const long long*)p)[e];
    return ((const int*)p)[e];
}

// ---------------------------------------------------------------------------
// Kernel 0: detect index dtype (int64 -> all high words zero).
// ---------------------------------------------------------------------------
__global__ void detect_kernel(const unsigned int* __restrict__ ec_raw)
{
    if (blockIdx.x == 0 && threadIdx.x == 0) {
        int nz = 0;
        #pragma unroll 8
        for (int i = 1; i < 256; i += 2) nz += (ec_raw[i] != 0u);
        g_is64 = (nz == 0) ? 1 : 0;
    }
}

// ---------------------------------------------------------------------------
// Kernel 1: inverse norms. Half-warp per node, float4 loads.
// ---------------------------------------------------------------------------
__global__ void invnorm_kernel(const float4* __restrict__ x)
{
    int t    = blockIdx.x * blockDim.x + threadIdx.x;
    int node = t >> 4;                     // half-warp per node
    int sub  = t & 15;
    if (node >= N_NODES) return;

    float4 a = x[node * D_F4 + sub];
    float s = a.x * a.x + a.y * a.y + a.z * a.z + a.w * a.w;
    #pragma unroll
    for (int o = 8; o; o >>= 1) s += __shfl_xor_sync(0xffffffffu, s, o);
    if (sub == 0) g_inv[node] = rsqrtf(s);
}

// ---------------------------------------------------------------------------
// Kernel 2: CSR row pointers from sorted edge_row via binary search.
// ---------------------------------------------------------------------------
__global__ void rowptr_kernel(const void* __restrict__ edge_row)
{
    int i = blockIdx.x * blockDim.x + threadIdx.x;
    if (i > N_NODES) return;

    int is64 = g_is64;
    int lo = 0, hi = N_EDGES;
    while (lo < hi) {
        int mid = (lo + hi) >> 1;
        if (get_idx(edge_row, mid, is64) < i) lo = mid + 1; else hi = mid;
    }
    g_rowptr[i] = lo;
}

// ---------------------------------------------------------------------------
// Kernel 3: fused sim + softmax + SPMM. HALF-WARP per row, float4 features.
// Softmax computed as w = exp(beta*cos - beta)  (shift-invariant, cos<=1 so
// the argument is <= 0: no overflow, no running max needed).
// Both halves of a warp run in lockstep for max(n_lo, n_hi) iterations with
// predication, so full-mask shuffles remain legal.
// ---------------------------------------------------------------------------
__global__ void fused_row_kernel(const float4* __restrict__ x,
                                 const void* __restrict__ edge_col,
                                 const float* __restrict__ beta,
                                 float4* __restrict__ out)
{
    int t    = blockIdx.x * blockDim.x + threadIdx.x;
    int row  = t >> 4;                     // half-warp per row
    int sub  = t & 15;
    if (row >= N_NODES) return;

    int is64 = g_is64;
    int s  = g_rowptr[row];
    int n  = g_rowptr[row + 1] - s;

    // lockstep trip count across the two half-warps
    int n_other = __shfl_xor_sync(0xffffffffu, n, 16);
    int nIter   = n > n_other ? n : n_other;

    float4 xr    = x[row * D_F4 + sub];
    float  invnr = g_inv[row];
    float  bv    = beta[0];
    float  bs    = bv * invnr;             // fold row inv-norm into scale

    float  wsum = 0.f;
    float4 acc  = make_float4(0.f, 0.f, 0.f, 0.f);

    #pragma unroll 2
    for (int i = 0; i < nIter; ++i) {
        bool valid = (i < n);
        int  c     = valid ? get_idx(edge_col, s + i, is64) : row;

        float4 b     = x[c * D_F4 + sub];
        float  invnc = g_inv[c];

        float d = xr.x * b.x + xr.y * b.y + xr.z * b.z + xr.w * b.w;
        #pragma unroll
        for (int o = 8; o; o >>= 1) d += __shfl_xor_sync(0xffffffffu, d, o);

        // w = exp(beta*cos - beta); arg <= 0 always
        float w = __expf(fmaf(bs * invnc, d, -bv));
        w = valid ? w : 0.f;

        wsum  += w;
        acc.x  = fmaf(w, b.x, acc.x);
        acc.y  = fmaf(w, b.y, acc.y);
        acc.z  = fmaf(w, b.z, acc.z);
        acc.w  = fmaf(w, b.w, acc.w);
    }

    float inv = (n > 0) ? (1.f / wsum) : 0.f;
    out[row * D_F4 + sub] = make_float4(acc.x * inv, acc.y * inv,
                                        acc.z * inv, acc.w * inv);
}

// ---------------------------------------------------------------------------
extern "C" void kernel_launch(void* const* d_in, const int* in_sizes, int n_in,
                              void* d_out, int out_size)
{
    const float4* x    = 0;
    const float*  beta = 0;
    const void*   er   = 0;
    const void*   ec   = 0;
    for (int i = 0; i < n_in; ++i) {
        long long sz = in_sizes[i];
        if (sz == (long long)N_NODES * D_FEAT) x = (const float4*)d_in[i];
        else if (sz == 1)                      beta = (const float*)d_in[i];
        else if (sz == N_EDGES) {
            if (!er) er = d_in[i]; else ec = d_in[i];
        }
    }
    float4* out = (float4*)d_out;

    detect_kernel<<<1, 32>>>((const unsigned int*)ec);

    {   // inverse norms: half-warp per node
        int threads = 256;
        long long total = (long long)N_NODES * 16;
        int blocks = (int)((total + threads - 1) / threads);
        invnorm_kernel<<<blocks, threads>>>(x);
    }
    {   // row pointers
        int threads = 256;
        int blocks = (N_NODES + 1 + threads - 1) / threads;
        rowptr_kernel<<<blocks, threads>>>(er);
    }
    {   // fused: half-warp per row
        int threads = 256;
        long long total = (long long)N_NODES * 16;
        int blocks = (int)((total + threads - 1) / threads);
        fused_row_kernel<<<blocks, threads>>>(x, ec, beta, out);
    }
}

// round 6
// speedup vs baseline: 3.3989x; 1.3550x over previous
#include <cuda_runtime.h>
#include <math.h>

#define N_NODES 100000
#define N_EDGES 1600000
#define D_FEAT  64
#define EPS     1e-7f
#define FULL    0xffffffffu

// Scratch
__device__ float g_inv[N_NODES];          // 1 / ||x_i||
__device__ int   g_col[N_EDGES];          // edge_col as int32
__device__ int   g_rowptr[N_NODES + 1];

// ---------------------------------------------------------------------------
// Inline dtype detection: edge values are random in [0, N_NODES); if int64,
// the high 32-bit words are all zero. 8 odd words -> P(false int64) ~ 1e-40.
// ---------------------------------------------------------------------------
__device__ __forceinline__ int detect_is64(const unsigned int* ec_raw)
{
    unsigned acc = 0;
    #pragma unroll
    for (int i = 1; i < 16; i += 2) acc |= ec_raw[i];
    return acc == 0u;
}

__device__ __forceinline__ int get_idx(const void* p, int e, int is64)
{
    if (is64) return (int)((const long long*)p)[e];
    return ((const int*)p)[e];
}

// ---------------------------------------------------------------------------
// Prep kernel: block-range split does three independent jobs in one launch.
//   blocks [0, B_NORM)            : inverse norms (half-warp per node)
//   blocks [B_NORM, B_NORM+B_COL) : edge_col -> int32
//   blocks [.., +B_ROW)           : CSR row pointers (binary search)
// ---------------------------------------------------------------------------
#define B_NORM 6250     // N_NODES*16 / 256
#define B_COL  6250     // N_EDGES / 256
#define B_ROW  391      // (N_NODES+1) / 256 rounded up

__global__ void __launch_bounds__(256)
prep_kernel(const float4* __restrict__ x4,
            const void* __restrict__ er,
            const void* __restrict__ ec)
{
    int b = blockIdx.x;
    if (b < B_NORM) {
        int t    = b * 256 + threadIdx.x;
        int node = t >> 4;
        int sub  = t & 15;
        if (node >= N_NODES) return;
        float4 a = x4[node * 16 + sub];
        float s = a.x * a.x + a.y * a.y + a.z * a.z + a.w * a.w;
        #pragma unroll
        for (int o = 8; o; o >>= 1) s += __shfl_xor_sync(FULL, s, o);
        if (sub == 0) g_inv[node] = rsqrtf(s);
    } else if (b < B_NORM + B_COL) {
        int e = (b - B_NORM) * 256 + threadIdx.x;
        if (e >= N_EDGES) return;
        int is64 = detect_is64((const unsigned int*)ec);
        g_col[e] = get_idx(ec, e, is64);
    } else {
        int i = (b - B_NORM - B_COL) * 256 + threadIdx.x;
        if (i > N_NODES) return;
        int is64 = detect_is64((const unsigned int*)ec);
        int lo = 0, hi = N_EDGES;
        while (lo < hi) {
            int mid = (lo + hi) >> 1;
            if (get_idx(er, mid, is64) < i) lo = mid + 1; else hi = mid;
        }
        g_rowptr[i] = lo;
    }
}

// ---------------------------------------------------------------------------
// Fused sim + softmax + SPMM. ONE WARP PER ROW.
// Lane = (group g in 0..3) x (feature f in 0..7): 4 edges in flight, each
// edge's 64-float feature row split across 8 lanes as two 128B-contiguous
// float4 loads. Softmax as w = exp(beta*(cos-1)) (shift-invariant, arg<=0).
// ---------------------------------------------------------------------------
__global__ void __launch_bounds__(256)
fused_row_kernel(const float4* __restrict__ x4,
                 const float* __restrict__ beta,
                 float4* __restrict__ out4)
{
    int warp = (blockIdx.x * blockDim.x + threadIdx.x) >> 5;
    if (warp >= N_NODES) return;
    int lane = threadIdx.x & 31;
    int g = lane >> 3;                    // edge slot within iteration
    int f = lane & 7;                     // feature slice

    int row = warp;
    int s = g_rowptr[row];
    int n = g_rowptr[row + 1] - s;

    float4 xr0 = x4[row * 16 + f];        // floats [4f, 4f+4)
    float4 xr1 = x4[row * 16 + 8 + f];    // floats [32+4f, 32+4f+4)
    float  bv  = beta[0];
    float  bs  = bv * g_inv[row];         // beta / ||x_r||

    float4 acc0 = make_float4(0.f, 0.f, 0.f, 0.f);
    float4 acc1 = make_float4(0.f, 0.f, 0.f, 0.f);
    float  wsum = 0.f;

    const int* __restrict__ col = g_col;

    for (int base = 0; base < n; base += 32) {
        int rem = n - base;
        // cooperative prefetch of 32 indices + their inverse norms
        int   myc   = (lane < rem) ? col[s + base + lane] : row;
        float myinv = g_inv[myc];
        int iters = (rem >= 32) ? 8 : ((rem + 3) >> 2);

        #pragma unroll 2
        for (int it = 0; it < iters; ++it) {
            int   src   = it * 4 + g;
            int   c     = __shfl_sync(FULL, myc, src);
            float invnc = __shfl_sync(FULL, myinv, src);
            bool  valid = (base + src) < n;

            float4 b0 = x4[c * 16 + f];
            float4 b1 = x4[c * 16 + 8 + f];

            float d = b0.x * xr0.x + b0.y * xr0.y + b0.z * xr0.z + b0.w * xr0.w
                    + b1.x * xr1.x + b1.y * xr1.y + b1.z * xr1.z + b1.w * xr1.w;
            d += __shfl_xor_sync(FULL, d, 1);
            d += __shfl_xor_sync(FULL, d, 2);
            d += __shfl_xor_sync(FULL, d, 4);

            float w = __expf(fmaf(bs * invnc, d, -bv));  // exp(beta*(cos-1))
            w = valid ? w : 0.f;

            wsum  += w;
            acc0.x = fmaf(w, b0.x, acc0.x);
            acc0.y = fmaf(w, b0.y, acc0.y);
            acc0.z = fmaf(w, b0.z, acc0.z);
            acc0.w = fmaf(w, b0.w, acc0.w);
            acc1.x = fmaf(w, b1.x, acc1.x);
            acc1.y = fmaf(w, b1.y, acc1.y);
            acc1.z = fmaf(w, b1.z, acc1.z);
            acc1.w = fmaf(w, b1.w, acc1.w);
        }
    }

    // reduce the 4 edge-groups' partial sums (butterfly -> all lanes hold total)
    #pragma unroll
    for (int o = 8; o <= 16; o <<= 1) {
        acc0.x += __shfl_xor_sync(FULL, acc0.x, o);
        acc0.y += __shfl_xor_sync(FULL, acc0.y, o);
        acc0.z += __shfl_xor_sync(FULL, acc0.z, o);
        acc0.w += __shfl_xor_sync(FULL, acc0.w, o);
        acc1.x += __shfl_xor_sync(FULL, acc1.x, o);
        acc1.y += __shfl_xor_sync(FULL, acc1.y, o);
        acc1.z += __shfl_xor_sync(FULL, acc1.z, o);
        acc1.w += __shfl_xor_sync(FULL, acc1.w, o);
        wsum   += __shfl_xor_sync(FULL, wsum,   o);
    }

    if (g == 0) {
        float inv = (n > 0) ? (1.f / wsum) : 0.f;
        out4[row * 16 + f]     = make_float4(acc0.x * inv, acc0.y * inv,
                                             acc0.z * inv, acc0.w * inv);
        out4[row * 16 + 8 + f] = make_float4(acc1.x * inv, acc1.y * inv,
                                             acc1.z * inv, acc1.w * inv);
    }
}

// ---------------------------------------------------------------------------
extern "C" void kernel_launch(void* const* d_in, const int* in_sizes, int n_in,
                              void* d_out, int out_size)
{
    const float4* x    = 0;
    const float*  beta = 0;
    const void*   er   = 0;
    const void*   ec   = 0;
    for (int i = 0; i < n_in; ++i) {
        long long sz = in_sizes[i];
        if (sz == (long long)N_NODES * D_FEAT) x = (const float4*)d_in[i];
        else if (sz == 1)                      beta = (const float*)d_in[i];
        else if (sz == N_EDGES) {
            if (!er) er = d_in[i]; else ec = d_in[i];
        }
    }
    float4* out = (float4*)d_out;

    prep_kernel<<<B_NORM + B_COL + B_ROW, 256>>>(x, er, ec);

    {   // one warp per row
        long long total = (long long)N_NODES * 32;
        int blocks = (int)((total + 255) / 256);
        fused_row_kernel<<<blocks, 256>>>(x, beta, out);
    }
}